// round 9
// baseline (speedup 1.0000x reference)
#include <cuda_runtime.h>
#include <cuda_fp16.h>
#include <cstdint>
#include <cstdlib>

// Problem dims (fixed by the reference)
#define CC 16
#define ZD 20
#define YD 256
#define XD 256
#define ZYX (ZD * YD * XD)   // 1,310,720 = 5120 * 256 exactly
#define NSLOT 256
#define NEDGE 32

// ---------------------------------------------------------------------------
// Device scratch (static __device__ arrays; no cudaMalloc allowed)
//   g_vec: point-major fp16 copy of vec, 2 uint4 (16 half) per point
//   g_lm : packed per-point {half maskv (low 16), uint16 label (high 16)}
// ---------------------------------------------------------------------------
__device__ uint4 g_vec[(size_t)ZYX * 2];   // 42 MB
__device__ uint32_t g_lm[ZYX];             // 5.2 MB
__device__ double g_loss[NSLOT];
__device__ double g_cnt[NSLOT];
__device__ unsigned int g_ticket = 0;

// ---------------------------------------------------------------------------
// Compile-time MT19937 reproducing np.random.RandomState(0)'s edge stream.
// Identical logic to the runtime version verified exact in R1/R4 (rel_err 0).
// 192 draws < 624, so exactly one twist.
// ---------------------------------------------------------------------------
struct CEdges { int dz[NEDGE]; int dy[NEDGE]; int dx[NEDGE]; int off[NEDGE]; };

__host__ __device__ constexpr uint32_t mt_temper(uint32_t y) {
    y ^= y >> 11;
    y ^= (y << 7)  & 0x9d2c5680u;
    y ^= (y << 15) & 0xefc60000u;
    y ^= y >> 18;
    return y;
}

__host__ __device__ constexpr CEdges gen_edges_ce() {
    uint32_t mt[624] = {};
    {
        uint32_t s = 0u;
        for (int i = 0; i < 624; i++) {
            mt[i] = s;
            s = 1812433253u * (s ^ (s >> 30)) + (uint32_t)(i + 1);
        }
    }
    for (int i = 0; i < 624; i++) {   // one twist (in place, standard order)
        uint32_t y = (mt[i] & 0x80000000u) | (mt[(i + 1) % 624] & 0x7fffffffu);
        mt[i] = mt[(i + 397) % 624] ^ (y >> 1) ^ ((y & 1u) ? 0x9908b0dfu : 0u);
    }
    CEdges E = {};
    int k = 0;
    for (int e = 0; e < NEDGE; e++) {
        int x = (int)(mt_temper(mt[k++]) & 31u);      // randint(0, 32)
        int y = (int)(mt_temper(mt[k++]) & 31u);      // randint(0, 32)
        int z = (int)(mt_temper(mt[k++]) & 15u);      // randint(0, 16)
        int sz = (mt_temper(mt[k++]) & 1u) ? -1 : 1;  // choice([1,-1]) z
        int sy = (mt_temper(mt[k++]) & 1u) ? -1 : 1;  // y
        int sx = (mt_temper(mt[k++]) & 1u) ? -1 : 1;  // x
        E.dz[e] = z * sz;
        E.dy[e] = y * sy;
        E.dx[e] = x * sx;
        E.off[e] = (E.dz[e] * YD + E.dy[e]) * XD + E.dx[e];
    }
    return E;
}

// ---------------------------------------------------------------------------
// Pass 1: transpose vec -> point-major fp16, pack mask*(label!=0) + label.
// Block 0 also zeroes the reduction slots (stream-ordered before fused pass).
// ---------------------------------------------------------------------------
__global__ void __launch_bounds__(256) pack_kernel(
    const float* __restrict__ vec,
    const int*   __restrict__ label,
    const float* __restrict__ mask)
{
    int p = blockIdx.x * 256 + threadIdx.x;   // grid exactly covers ZYX

    __align__(16) __half2 h[8];
#pragma unroll
    for (int c = 0; c < 8; c++) {
        float a = __ldg(vec + (size_t)(2 * c + 0) * ZYX + p);
        float b = __ldg(vec + (size_t)(2 * c + 1) * ZYX + p);
        h[c] = __floats2half2_rn(a, b);
    }
    g_vec[(size_t)p * 2 + 0] = *(const uint4*)&h[0];
    g_vec[(size_t)p * 2 + 1] = *(const uint4*)&h[4];

    int   l = __ldg(label + p);
    float m = __ldg(mask + p) * (l != 0 ? 1.0f : 0.0f);
    uint32_t hm = (uint32_t)__half_as_ushort(__float2half_rn(m));
    g_lm[p] = hm | ((uint32_t)(l & 0xFFFF) << 16);

    if (blockIdx.x == 0) {
        g_loss[threadIdx.x] = 0.0;
        g_cnt[threadIdx.x]  = 0.0;
    }
}

// ---------------------------------------------------------------------------
// Pass 2: fused over all 32 (compile-time) edges. Thread owns point
// p = (z,y,x); for each edge delta computes the pair (p, p-delta) iff
// p-delta is in bounds (exactly the reference crop-pair set).
// Dot product entirely in HFMA2 — no converts in the inner loop.
// Last block finalizes to out.
// ---------------------------------------------------------------------------
__global__ void __launch_bounds__(256) fused_kernel(float* __restrict__ out) {
    constexpr CEdges CE = gen_edges_ce();

    int zy = blockIdx.x;          // 0..5119
    int z  = zy >> 8;
    int y  = zy & 255;
    int x  = threadIdx.x;
    int p  = (zy << 8) | x;

    // Self channel vector as 8 half2 registers
    uint4 a0 = g_vec[(size_t)p * 2 + 0];
    uint4 a1 = g_vec[(size_t)p * 2 + 1];
    __half2 sa[8];
    sa[0] = *(__half2*)&a0.x; sa[1] = *(__half2*)&a0.y;
    sa[2] = *(__half2*)&a0.z; sa[3] = *(__half2*)&a0.w;
    sa[4] = *(__half2*)&a1.x; sa[5] = *(__half2*)&a1.y;
    sa[6] = *(__half2*)&a1.z; sa[7] = *(__half2*)&a1.w;

    uint32_t lms = g_lm[p];
    float ms = __half2float(__ushort_as_half((unsigned short)(lms & 0xFFFF)));
    int   ls = (int)(lms >> 16);

    float loss = 0.0f, cnt = 0.0f;

#pragma unroll
    for (int e = 0; e < NEDGE; e++) {
        if ((unsigned)(z - CE.dz[e]) < (unsigned)ZD &&
            (unsigned)(y - CE.dy[e]) < (unsigned)YD &&
            (unsigned)(x - CE.dx[e]) < (unsigned)XD)
        {
            int q = p - CE.off[e];
            uint4 b0 = __ldg(&g_vec[(size_t)q * 2 + 0]);
            uint4 b1 = __ldg(&g_vec[(size_t)q * 2 + 1]);
            const __half2* hb0 = (const __half2*)&b0;
            const __half2* hb1 = (const __half2*)&b1;

            // 16-dim dot in half2: 2 HMUL2 + 6 HFMA2 + 1 HADD2, then to fp32
            __half2 acc0 = __hmul2(sa[0], hb0[0]);
            __half2 acc1 = __hmul2(sa[1], hb0[1]);
            acc0 = __hfma2(sa[2], hb0[2], acc0);
            acc1 = __hfma2(sa[3], hb0[3], acc1);
            acc0 = __hfma2(sa[4], hb1[0], acc0);
            acc1 = __hfma2(sa[5], hb1[1], acc1);
            acc0 = __hfma2(sa[6], hb1[2], acc0);
            acc1 = __hfma2(sa[7], hb1[3], acc1);
            float2 f = __half22float2(__hadd2(acc0, acc1));
            float pred = f.x + f.y;

            uint32_t lmq = __ldg(&g_lm[q]);
            float mq = __half2float(__ushort_as_half((unsigned short)(lmq & 0xFFFF)));
            int   lq = (int)(lmq >> 16);

            float w   = ms * mq;
            float tgt = (ls == lq) ? 1.0f : 0.0f;
            float ap  = fabsf(pred);
            // stable BCE-with-logits; 1+e in [1,2] -> no cancellation in __logf
            float bce = fmaxf(pred, 0.0f) - pred * tgt + __logf(1.0f + __expf(-ap));

            loss = fmaf(w, bce, loss);
            cnt += (w > 0.0f) ? 1.0f : 0.0f;
        }
    }

    // Block reduction: warp shuffle, then smem across 8 warps.
#pragma unroll
    for (int s = 16; s > 0; s >>= 1) {
        loss += __shfl_down_sync(0xFFFFFFFFu, loss, s);
        cnt  += __shfl_down_sync(0xFFFFFFFFu, cnt,  s);
    }
    __shared__ float sl[8], sc[8];
    int lane = threadIdx.x & 31;
    int wid  = threadIdx.x >> 5;
    if (lane == 0) { sl[wid] = loss; sc[wid] = cnt; }
    __syncthreads();
    if (wid == 0) {
        loss = (lane < 8) ? sl[lane] : 0.0f;
        cnt  = (lane < 8) ? sc[lane] : 0.0f;
#pragma unroll
        for (int s = 4; s > 0; s >>= 1) {
            loss += __shfl_down_sync(0xFFFFFFFFu, loss, s);
            cnt  += __shfl_down_sync(0xFFFFFFFFu, cnt,  s);
        }
        if (lane == 0) {
            int slot = blockIdx.x & (NSLOT - 1);
            atomicAdd(&g_loss[slot], (double)loss);
            atomicAdd(&g_cnt[slot],  (double)cnt);
        }
    }

    // Last-block finalize (threadFenceReduction pattern).
    __shared__ bool amLast;
    if (threadIdx.x == 0) {
        __threadfence();
        unsigned int t = atomicAdd(&g_ticket, 1u);
        amLast = (t == (unsigned)gridDim.x - 1u);
    }
    __syncthreads();
    if (amLast) {
        __threadfence();
        int i = threadIdx.x;
        double l = g_loss[i];
        double c = g_cnt[i];
#pragma unroll
        for (int s = 16; s > 0; s >>= 1) {
            l += __shfl_down_sync(0xFFFFFFFFu, l, s);
            c += __shfl_down_sync(0xFFFFFFFFu, c, s);
        }
        __shared__ double dl[8], dc[8];
        if (lane == 0) { dl[wid] = l; dc[wid] = c; }
        __syncthreads();
        if (wid == 0) {
            l = (lane < 8) ? dl[lane] : 0.0;
            c = (lane < 8) ? dc[lane] : 0.0;
#pragma unroll
            for (int s = 4; s > 0; s >>= 1) {
                l += __shfl_down_sync(0xFFFFFFFFu, l, s);
                c += __shfl_down_sync(0xFFFFFFFFu, c, s);
            }
            if (lane == 0) {
                out[0] = (float)l;
                out[1] = (float)c;
                g_ticket = 0;   // reset for next (deterministic) replay
            }
        }
    }
}

extern "C" void kernel_launch(void* const* d_in, const int* in_sizes, int n_in,
                              void* d_out, int out_size) {
    const float* vec   = (const float*)d_in[0];
    const int*   label = (const int*)d_in[1];
    const float* mask  = (const float*)d_in[2];
    float* out = (float*)d_out;

    pack_kernel<<<ZYX / 256, 256>>>(vec, label, mask);
    fused_kernel<<<ZD * YD, 256>>>(out);
}